// round 13
// baseline (speedup 1.0000x reference)
#include <cuda_runtime.h>

#define T_STEPS 300
#define DIMX 40
#define HID 64
#define KDIM 104          // DIMX + HID
#define NGATE 256
#define BATCH 2048
#define ROWS 14
#define NBLK 147
#define OUTD 512

// LSTM smem: just the A double buffer, 2 * 14*104*4 = 11648 B
#define OFF_A0  0
#define OFF_A1  5824
#define SMEM1   11648

// head smem: fs[8*64] + W1s[64*128] + y1s[8*128] + ls[8*512]
#define SMEM_H  ((8*64 + 64*128 + 8*128 + 8*512) * 4)

__device__ float g_final[BATCH * HID];
__device__ float g_c[BATCH * HID];
__device__ float g_h[BATCH * HID];

__device__ __forceinline__ float fast_rcp(float x) {
    float y; asm("rcp.approx.f32 %0, %1;" : "=f"(y) : "f"(x)); return y;
}
__device__ __forceinline__ float tanh_fast(float x) {
    float y; asm("tanh.approx.f32 %0, %1;" : "=f"(y) : "f"(x)); return y;
}
__device__ __forceinline__ unsigned long long pack2(float a, float b) {
    unsigned long long r;
    asm("mov.b64 %0, {%1, %2};" : "=l"(r) : "f"(a), "f"(b));
    return r;
}
__device__ __forceinline__ float2 unpack2(unsigned long long v) {
    float2 r;
    asm("mov.b64 {%0, %1}, %2;" : "=f"(r.x), "=f"(r.y) : "l"(v));
    return r;
}
#define FMA2(d, a, b) asm("fma.rn.f32x2 %0, %1, %2, %0;" : "+l"(d) : "l"(a), "l"(b))

// ---------------------------------------------------------------------------
// Persistent LSTM, weights in REGISTERS (B is step-invariant; smem B reads
// were the dominant non-FMA stream in R4-R6 profiles).
//   256 threads, all covering all 14 rows. lane = kw*16 + hq*2 + gp,
//   h = warp*8 + hq. Thread owns gates {2gp, 2gp+1} of unit h over k-half kw.
//   B slice = 26 k-pairs x 2 gates = 52 u64 registers, loaded once from Wk.
// GEMM inner loop: dual-address broadcast LDS.128 of A (kw halves 208B apart,
//   conflict-free) + 4 FMA2 per row per 4-k chunk. No B loads.
// Epilogue: hsum + shfl_xor(16) k-merge + shfl_xor(1) gate exchange (R5
//   pattern) + local cell update; (gp==0 && kw==0) lane writes h.
// A double-buffered; one __syncthreads per step.
// ---------------------------------------------------------------------------
__global__ __launch_bounds__(256, 1) void lstm_kernel(
    const float* __restrict__ X,      // [B][T][40]
    const int*   __restrict__ seq,    // [B]
    const float* __restrict__ Wk,     // [104][256]
    const float* __restrict__ bias,   // [256]
    int t0, int t1)
{
    extern __shared__ char smem[];
    float* Abuf[2] = { (float*)(smem + OFF_A0), (float*)(smem + OFF_A1) };

    const int tid  = threadIdx.x;
    const int g0   = blockIdx.x * ROWS;
    const int lane = tid & 31;
    const int w    = tid >> 5;
    const int gp   = lane & 1;          // gate pair: 0={i,j} 1={f,o}
    const int hq   = (lane >> 1) & 7;
    const int kw   = lane >> 4;         // k half
    const int h    = w * 8 + hq;        // hidden unit 0..63

    // ---- preload B slice into registers: 26 kp x 2 gates ----
    unsigned long long Breg[26][2];
    {
        const int colA = (2 * gp) * 64 + h;       // gate 2gp
        const int colB = (2 * gp + 1) * 64 + h;   // gate 2gp+1
        const float* Wb = Wk + (kw * 52) * NGATE;
        #pragma unroll
        for (int kp = 0; kp < 26; kp++) {
            const float* r0 = Wb + (2 * kp) * NGATE;
            const float* r1 = Wb + (2 * kp + 1) * NGATE;
            Breg[kp][0] = pack2(__ldg(r0 + colA), __ldg(r1 + colA));
            Breg[kp][1] = pack2(__ldg(r0 + colB), __ldg(r1 + colB));
        }
    }

    // ---- zero h region of both buffers ----
    for (int i = tid; i < ROWS * HID; i += 256) {
        int r = i / HID, hh = i % HID;
        Abuf[0][r * KDIM + DIMX + hh] = 0.0f;
        Abuf[1][r * KDIM + DIMX + hh] = 0.0f;
    }

    // ---- x streaming: 560 elems/step, 3 slots per thread ----
    const float* xp[3];
    bool vld[3];
    int  sloc[3];
    #pragma unroll
    for (int s = 0; s < 3; s++) {
        int e = tid + 256 * s;
        bool inr = e < ROWS * DIMX;
        int r = inr ? e / DIMX : 0;
        vld[s]  = inr && ((g0 + r) < BATCH);
        sloc[s] = inr ? (r * KDIM + e % DIMX) : 0;
        xp[s]   = X + (size_t)(g0 + (vld[s] ? r : 0)) * (T_STEPS * DIMX) + (e % DIMX);
    }
    #pragma unroll
    for (int s = 0; s < 3; s++) {
        if (tid + 256 * s < ROWS * DIMX)
            Abuf[0][sloc[s]] = vld[s] ? __ldg(xp[s] + t0 * DIMX) : 0.0f;
    }

    // ---- per-thread bias / activation constants (R5 pattern) ----
    // gp=0: gates (i, j);  gp=1: gates (f+1, o)
    const float b0r = gp ? (__ldg(bias + 128 + h) + 1.0f) : __ldg(bias + h);
    const float b1r = gp ? __ldg(bias + 192 + h) : __ldg(bias + 64 + h);
    const float s1  = gp ? 0.5f : 1.0f;   // a1 = tanh(v1*s1)*s1 + h1
    const float h1  = gp ? 0.5f : 0.0f;

    // ---- per-row state (all 14 rows per thread) ----
    float creg[ROWS];
    int   idxr[ROWS];
    #pragma unroll
    for (int r = 0; r < ROWS; r++) {
        int row = g0 + r;
        bool ok = row < BATCH;
        idxr[r] = ok ? (__ldg(seq + row) - 1) : -2;
        if (t0 == 0) {
            creg[r] = 0.0f;
        } else {
            creg[r] = ok ? g_c[(size_t)row * HID + h] : 0.0f;
            if (gp == 0 && kw == 0)
                Abuf[0][r * KDIM + DIMX + h] = ok ? g_h[(size_t)row * HID + h] : 0.0f;
        }
    }
    const bool writer = (gp == 0) && (kw == 0);
    float* finalp = g_final + (size_t)g0 * HID + h;

    __syncthreads();

    int p = 0;
    for (int t = t0; t < t1; t++) {
        float* Ap = Abuf[p];
        float* Aq = Abuf[1 - p];

        // prefetch x_{t+1}
        float xr[3];
        const bool pf = (t + 1 < T_STEPS);
        if (pf) {
            const int off = (t + 1) * DIMX;
            #pragma unroll
            for (int s = 0; s < 3; s++) xr[s] = vld[s] ? __ldg(xp[s] + off) : 0.0f;
        }

        // ---- GEMM: 14 rows x 2 gates over this thread's 52-k half ----
        unsigned long long acc[ROWS][2];
        #pragma unroll
        for (int r = 0; r < ROWS; r++) { acc[r][0] = 0ULL; acc[r][1] = 0ULL; }
        const float* Arow = Ap + kw * 52;

        #pragma unroll
        for (int it = 0; it < 13; it++) {           // 4 k per iter = kp 2it, 2it+1
            #pragma unroll
            for (int r = 0; r < ROWS; r++) {
                ulonglong2 a = *(const ulonglong2*)(Arow + r * KDIM + it * 4);
                FMA2(acc[r][0], a.x, Breg[2 * it][0]);
                FMA2(acc[r][1], a.x, Breg[2 * it][1]);
                FMA2(acc[r][0], a.y, Breg[2 * it + 1][0]);
                FMA2(acc[r][1], a.y, Breg[2 * it + 1][1]);
            }
        }

        // ---- stage x_{t+1} into next buffer ----
        if (pf) {
            #pragma unroll
            for (int s = 0; s < 3; s++) {
                if (tid + 256 * s < ROWS * DIMX) Aq[sloc[s]] = xr[s];
            }
        }

        // ---- epilogue: kw merge, activations, gate exchange, cell update ----
        #pragma unroll
        for (int r = 0; r < ROWS; r++) {
            float2 p0 = unpack2(acc[r][0]);
            float2 p1 = unpack2(acc[r][1]);
            float v0 = p0.x + p0.y;
            float v1 = p1.x + p1.y;
            v0 += __shfl_xor_sync(0xffffffffu, v0, 16);   // merge k halves
            v1 += __shfl_xor_sync(0xffffffffu, v1, 16);
            v0 += b0r;                                    // i or f(+1)
            v1 += b1r;                                    // j or o
            float a0 = 0.5f * tanh_fast(0.5f * v0) + 0.5f;    // ig or fg
            float a1 = tanh_fast(v1 * s1) * s1 + h1;          // jg or og
            float o0 = __shfl_xor_sync(0xffffffffu, a0, 1);
            float o1 = __shfl_xor_sync(0xffffffffu, a1, 1);
            float ig = gp ? o0 : a0;
            float jg = gp ? o1 : a1;
            float fg = gp ? a0 : o0;
            float og = gp ? a1 : o1;
            float c  = creg[r] * fg + ig * jg;
            creg[r] = c;
            float hn = tanh_fast(c) * og;
            if (writer) {
                Aq[r * KDIM + DIMX + h] = hn;
                if (t == idxr[r]) finalp[r * HID] = hn;
            }
        }

        __syncthreads();
        p ^= 1;
    }

    // ---- save carry state if more steps remain ----
    if (t1 < T_STEPS && writer) {
        #pragma unroll
        for (int r = 0; r < ROWS; r++) {
            int row = g0 + r;
            if (row < BATCH) {
                g_c[(size_t)row * HID + h] = creg[r];
                g_h[(size_t)row * HID + h] = Abuf[p][r * KDIM + DIMX + h];
            }
        }
    }
}

// ---------------------------------------------------------------------------
// Head: 256 blocks x 256 threads, 8 batch rows per block.
// ---------------------------------------------------------------------------
__global__ __launch_bounds__(256, 1) void head_kernel(
    const float* __restrict__ W1, const float* __restrict__ b1,
    const float* __restrict__ gamma, const float* __restrict__ beta,
    const float* __restrict__ mean, const float* __restrict__ var,
    const float* __restrict__ W2, const float* __restrict__ b2,
    float* __restrict__ out)
{
    extern __shared__ char smem[];
    float* fs  = (float*)smem;            // [8][64]
    float* W1s = fs + 8 * 64;             // [64][128]
    float* y1s = W1s + 64 * 128;          // [8][128]
    float* ls  = y1s + 8 * 128;           // [8][512]

    const int tid = threadIdx.x;
    const int g0  = blockIdx.x * 8;

    for (int i = tid; i < 8 * 64 / 4; i += 256)
        ((float4*)fs)[i] = ((const float4*)g_final)[g0 * 16 + i];
    for (int i = tid; i < 64 * 128 / 4; i += 256)
        ((float4*)W1s)[i] = ((const float4*)W1)[i];
    __syncthreads();

    // dense1 + relu + BN
    {
        const int c  = tid & 127;
        const int r0 = (tid >> 7) * 4;
        const float scale = gamma[c] * rsqrtf(var[c] + 1e-3f);
        const float shift = beta[c] - mean[c] * scale;
        const float bb = b1[c];
        #pragma unroll
        for (int r = r0; r < r0 + 4; r++) {
            float acc = bb;
            #pragma unroll 8
            for (int k = 0; k < 64; k++) acc += fs[r * 64 + k] * W1s[k * 128 + c];
            acc = fmaxf(acc, 0.0f);
            y1s[r * 128 + c] = acc * scale + shift;
        }
    }
    __syncthreads();

    // dense2: cols {2*tid, 2*tid+1}, k-packed f32x2
    {
        const int c0 = 2 * tid;
        unsigned long long acc[8][2];
        #pragma unroll
        for (int r = 0; r < 8; r++) { acc[r][0] = 0ULL; acc[r][1] = 0ULL; }

        #pragma unroll 4
        for (int kp2 = 0; kp2 < 32; kp2++) {
            const int k = 4 * kp2;
            float2 w0 = *(const float2*)(W2 + (size_t)(k    ) * OUTD + c0);
            float2 w1 = *(const float2*)(W2 + (size_t)(k + 1) * OUTD + c0);
            float2 w2 = *(const float2*)(W2 + (size_t)(k + 2) * OUTD + c0);
            float2 w3 = *(const float2*)(W2 + (size_t)(k + 3) * OUTD + c0);
            unsigned long long p01a = pack2(w0.x, w1.x);
            unsigned long long p23a = pack2(w2.x, w3.x);
            unsigned long long p01b = pack2(w0.y, w1.y);
            unsigned long long p23b = pack2(w2.y, w3.y);
            #pragma unroll
            for (int r = 0; r < 8; r++) {
                ulonglong2 y = *(const ulonglong2*)(y1s + r * 128 + k);
                FMA2(acc[r][0], y.x, p01a);
                FMA2(acc[r][0], y.y, p23a);
                FMA2(acc[r][1], y.x, p01b);
                FMA2(acc[r][1], y.y, p23b);
            }
        }
        const float bb0 = b2[c0], bb1 = b2[c0 + 1];
        #pragma unroll
        for (int r = 0; r < 8; r++) {
            float2 pa = unpack2(acc[r][0]);
            float2 pb = unpack2(acc[r][1]);
            ls[r * OUTD + c0]     = pa.x + pa.y + bb0;
            ls[r * OUTD + c0 + 1] = pb.x + pb.y + bb1;
        }
    }
    __syncthreads();

    // softmax: 8 warps, one row each
    {
        const int w = tid >> 5, lane = tid & 31;
        float v[16];
        float m = -1e30f;
        #pragma unroll
        for (int j = 0; j < 16; j++) {
            v[j] = ls[w * OUTD + lane + 32 * j];
            m = fmaxf(m, v[j]);
        }
        #pragma unroll
        for (int s = 16; s; s >>= 1) m = fmaxf(m, __shfl_xor_sync(0xffffffffu, m, s));
        float sum = 0.0f;
        #pragma unroll
        for (int j = 0; j < 16; j++) { v[j] = __expf(v[j] - m); sum += v[j]; }
        #pragma unroll
        for (int s = 16; s; s >>= 1) sum += __shfl_xor_sync(0xffffffffu, sum, s);
        const float inv = fast_rcp(sum);
        float* orow = out + (size_t)(g0 + w) * OUTD + lane;
        #pragma unroll
        for (int j = 0; j < 16; j++) orow[32 * j] = v[j] * inv;
    }
}

extern "C" void kernel_launch(void* const* d_in, const int* in_sizes, int n_in,
                              void* d_out, int out_size) {
    const float* X     = (const float*)d_in[0];
    const int*   seq   = (const int*)  d_in[1];
    const float* Wk    = (const float*)d_in[2];
    const float* bias  = (const float*)d_in[3];
    const float* W1    = (const float*)d_in[4];
    const float* b1    = (const float*)d_in[5];
    const float* gamma = (const float*)d_in[6];
    const float* beta  = (const float*)d_in[7];
    const float* mean  = (const float*)d_in[8];
    const float* var   = (const float*)d_in[9];
    const float* W2    = (const float*)d_in[10];
    const float* b2    = (const float*)d_in[11];
    float* out = (float*)d_out;

    cudaFuncSetAttribute(lstm_kernel, cudaFuncAttributeMaxDynamicSharedMemorySize, SMEM1);
    cudaFuncSetAttribute(head_kernel, cudaFuncAttributeMaxDynamicSharedMemorySize, SMEM_H);

    lstm_kernel<<<NBLK, 256, SMEM1>>>(X, seq, Wk, bias, 0, 150);
    lstm_kernel<<<NBLK, 256, SMEM1>>>(X, seq, Wk, bias, 150, 300);
    head_kernel<<<BATCH / 8, 256, SMEM_H>>>(W1, b1, gamma, beta, mean, var, W2, b2, out);
}

// round 16
// speedup vs baseline: 1.3685x; 1.3685x over previous
#include <cuda_runtime.h>

#define T_STEPS 300
#define DIMX 40
#define HID 64
#define KDIM 104          // DIMX + HID
#define NGATE 256
#define BATCH 2048
#define ROWS 14
#define NBLK 147
#define OUTD 512

// LSTM smem layout (bytes) — identical to the 994us R2 kernel
#define OFF_BP  0                         // B' interleaved k-pairs: 52*256*8 = 106496
#define OFF_A   106496                    // A plain f32: 14*104*4 = 5824
#define OFF_Z   112320                    // zs: 14*256*4 = 14336
#define SMEM1   126656

// head smem: fs[8*64] + W1s[64*128] + y1s[8*128] + ls[8*512]
#define SMEM_H  ((8*64 + 64*128 + 8*128 + 8*512) * 4)

__device__ float g_final[BATCH * HID];
__device__ float g_c[BATCH * HID];
__device__ float g_h[BATCH * HID];

__device__ __forceinline__ float fast_rcp(float x) {
    float y; asm("rcp.approx.f32 %0, %1;" : "=f"(y) : "f"(x)); return y;
}
__device__ __forceinline__ float tanh_fast(float x) {
    float y; asm("tanh.approx.f32 %0, %1;" : "=f"(y) : "f"(x)); return y;
}
__device__ __forceinline__ unsigned long long pack2(float a, float b) {
    unsigned long long r;
    asm("mov.b64 %0, {%1, %2};" : "=l"(r) : "f"(a), "f"(b));
    return r;
}
__device__ __forceinline__ float2 unpack2(unsigned long long v) {
    float2 r;
    asm("mov.b64 {%0, %1}, %2;" : "=f"(r.x), "=f"(r.y) : "l"(v));
    return r;
}
#define FMA2(d, a, b) asm("fma.rn.f32x2 %0, %1, %2, %0;" : "+l"(d) : "l"(a), "l"(b))

// ---------------------------------------------------------------------------
// Persistent LSTM — the 994us R2 structure (fastest measured across R2-R7),
// with ONLY the activations changed to single-MUFU tanh.approx (R2 used
// __expf+rcp: 2 MUFU + chain per sigmoid) and a t0/t1 split + state carry.
//
// 256 threads = 2 row-groups(7 rows) x 128 col-threads(2 gate-cols each).
// GEMM k-packed f32x2: A plain f32 (LDS.128 = 4k), B' = [52][256] u64 k-pairs.
// Gates go through smem zs (write -> bar -> cell threads read); single A
// buffer, h written back into A after BAR1, BAR2 closes the step.
// ---------------------------------------------------------------------------
__global__ __launch_bounds__(256, 1) void lstm_kernel(
    const float* __restrict__ X,      // [B][T][40]
    const int*   __restrict__ seq,    // [B]
    const float* __restrict__ Wk,     // [104][256]
    const float* __restrict__ bias,   // [256]
    int t0, int t1)
{
    extern __shared__ char smem[];
    unsigned long long* Bs = (unsigned long long*)(smem + OFF_BP);  // [52][256]
    float*              As = (float*)(smem + OFF_A);                 // [14][104]
    float*              zs = (float*)(smem + OFF_Z);                 // [14][256]

    const int tid = threadIdx.x;
    const int g0  = blockIdx.x * ROWS;

    // ---- build B' (interleaved k-pairs), col = tid ----
    {
        const int c = tid;
        #pragma unroll 4
        for (int kp = 0; kp < KDIM / 2; kp++) {
            float w0 = __ldg(Wk + (2 * kp)     * NGATE + c);
            float w1 = __ldg(Wk + (2 * kp + 1) * NGATE + c);
            Bs[kp * NGATE + c] = pack2(w0, w1);
        }
    }
    // ---- init h region of A (zero or carried state) ----
    for (int i = tid; i < ROWS * HID; i += 256) {
        int r = i / HID, hh = i % HID;
        float hv = 0.0f;
        if (t0 > 0 && (g0 + r) < BATCH) hv = g_h[(size_t)(g0 + r) * HID + hh];
        As[r * KDIM + DIMX + hh] = hv;
    }

    // ---- x streaming: 560 elems/step, <=3 per thread ----
    const int e0 = tid;
    const int e1 = tid + 256;
    const int e2 = tid + 512;
    const bool v0 = (g0 + e0 / DIMX) < BATCH;
    const bool v1 = (e1 < ROWS * DIMX) && ((g0 + e1 / DIMX) < BATCH);
    const bool v2 = (e2 < ROWS * DIMX) && ((g0 + e2 / DIMX) < BATCH);
    const float* xp0 = X + (size_t)(g0 + e0 / DIMX) * (T_STEPS * DIMX) + (e0 % DIMX);
    const float* xp1 = X + (size_t)(g0 + (v1 ? e1 / DIMX : 0)) * (T_STEPS * DIMX) + (e1 % DIMX);
    const float* xp2 = X + (size_t)(g0 + (v2 ? e2 / DIMX : 0)) * (T_STEPS * DIMX) + (e2 % DIMX);

    // x_{t0}
    {
        const int off = t0 * DIMX;
        float a = v0 ? __ldg(xp0 + off) : 0.0f;
        float b = v1 ? __ldg(xp1 + off) : 0.0f;
        float c = v2 ? __ldg(xp2 + off) : 0.0f;
        As[(e0 / DIMX) * KDIM + (e0 % DIMX)] = a;
        if (e1 < ROWS * DIMX) As[(e1 / DIMX) * KDIM + (e1 % DIMX)] = b;
        if (e2 < ROWS * DIMX) As[(e2 / DIMX) * KDIM + (e2 % DIMX)] = c;
    }

    // ---- GEMM mapping ----
    const int lane127 = tid & 127;
    const int c0    = 2 * lane127;            // 2 cols per thread
    const int rbase = (tid >> 7) * 7;         // 7 rows per group
    const int gate  = c0 >> 6;
    const ulonglong2* Bp = ((const ulonglong2*)Bs) + lane127;  // cols {c0, c0+1}
    const float fold = (gate == 2) ? 1.0f : 0.0f;              // forget bias
    const float bias0 = __ldg(bias + c0) + fold;
    const float bias1 = __ldg(bias + c0 + 1) + fold;

    // ---- cell mapping: tid<224, 4 cells each ----
    const int cr = tid >> 4;
    const int ch = (tid & 15) * 4;
    int myidx = -2;
    if (tid < 224 && (g0 + cr) < BATCH) myidx = seq[g0 + cr] - 1;
    float creg0 = 0.f, creg1 = 0.f, creg2 = 0.f, creg3 = 0.f;
    if (t0 > 0 && tid < 224 && (g0 + cr) < BATCH) {
        const float* cp = g_c + (size_t)(g0 + cr) * HID + ch;
        creg0 = cp[0]; creg1 = cp[1]; creg2 = cp[2]; creg3 = cp[3];
    }
    float* finalp = g_final + (size_t)(g0 + cr) * HID + ch;

    __syncthreads();

    for (int t = t0; t < t1; t++) {
        // prefetch x_{t+1}
        float xr0 = 0.f, xr1 = 0.f, xr2 = 0.f;
        const bool pf = (t + 1 < T_STEPS);
        if (pf) {
            const int off = (t + 1) * DIMX;
            if (v0) xr0 = __ldg(xp0 + off);
            if (v1) xr1 = __ldg(xp1 + off);
            if (v2) xr2 = __ldg(xp2 + off);
        }

        // ---- z = A @ W (k-packed f32x2) ----
        unsigned long long acc[7][2];
        #pragma unroll
        for (int r = 0; r < 7; r++) { acc[r][0] = 0ULL; acc[r][1] = 0ULL; }

        const ulonglong2* Ap = (const ulonglong2*)(As + rbase * KDIM);
        #pragma unroll 2
        for (int kp2 = 0; kp2 < KDIM / 4; kp2++) {   // 26 iters, 4 k each
            ulonglong2 b0 = Bp[(2 * kp2)     * 128];  // kp = 2*kp2
            ulonglong2 b1 = Bp[(2 * kp2 + 1) * 128];  // kp = 2*kp2+1
            #pragma unroll
            for (int r = 0; r < 7; r++) {
                ulonglong2 a = Ap[r * 26 + kp2];      // {k0,k1},{k2,k3}
                FMA2(acc[r][0], a.x, b0.x);
                FMA2(acc[r][1], a.x, b0.y);
                FMA2(acc[r][0], a.y, b1.x);
                FMA2(acc[r][1], a.y, b1.y);
            }
        }

        // ---- epilogue: horizontal add + bias + activation (single MUFU) ----
        #pragma unroll
        for (int r = 0; r < 7; r++) {
            float2 p0 = unpack2(acc[r][0]);
            float2 p1 = unpack2(acc[r][1]);
            float z0 = p0.x + p0.y + bias0;
            float z1 = p1.x + p1.y + bias1;
            float a0, a1;
            if (gate == 1) {           // j: tanh
                a0 = tanh_fast(z0);
                a1 = tanh_fast(z1);
            } else {                   // i, f(+1 folded), o: sigmoid
                a0 = 0.5f * tanh_fast(0.5f * z0) + 0.5f;
                a1 = 0.5f * tanh_fast(0.5f * z1) + 0.5f;
            }
            *(float2*)(zs + (rbase + r) * NGATE + c0) = make_float2(a0, a1);
        }
        __syncthreads();   // A reads done; zs visible

        // ---- stage x_{t+1} ----
        if (pf) {
            As[(e0 / DIMX) * KDIM + (e0 % DIMX)] = xr0;
            if (e1 < ROWS * DIMX) As[(e1 / DIMX) * KDIM + (e1 % DIMX)] = xr1;
            if (e2 < ROWS * DIMX) As[(e2 / DIMX) * KDIM + (e2 % DIMX)] = xr2;
        }

        // ---- cell update ----
        if (tid < 224) {
            const float* zrow = zs + cr * NGATE;
            float4 gi = *(const float4*)(zrow + ch);
            float4 gj = *(const float4*)(zrow + 64 + ch);
            float4 gf = *(const float4*)(zrow + 128 + ch);
            float4 go = *(const float4*)(zrow + 192 + ch);
            creg0 = creg0 * gf.x + gi.x * gj.x;
            creg1 = creg1 * gf.y + gi.y * gj.y;
            creg2 = creg2 * gf.z + gi.z * gj.z;
            creg3 = creg3 * gf.w + gi.w * gj.w;
            float h0 = tanh_fast(creg0) * go.x;
            float h1 = tanh_fast(creg1) * go.y;
            float h2 = tanh_fast(creg2) * go.z;
            float h3 = tanh_fast(creg3) * go.w;
            *(float4*)(As + cr * KDIM + DIMX + ch) = make_float4(h0, h1, h2, h3);
            if (t == myidx) {
                finalp[0] = h0; finalp[1] = h1; finalp[2] = h2; finalp[3] = h3;
            }
        }
        __syncthreads();   // A ready for next step
    }

    // ---- save carry state if more steps remain ----
    if (t1 < T_STEPS && tid < 224 && (g0 + cr) < BATCH) {
        float* cp = g_c + (size_t)(g0 + cr) * HID + ch;
        cp[0] = creg0; cp[1] = creg1; cp[2] = creg2; cp[3] = creg3;
        const float* hp = As + cr * KDIM + DIMX + ch;
        float* gh = g_h + (size_t)(g0 + cr) * HID + ch;
        gh[0] = hp[0]; gh[1] = hp[1]; gh[2] = hp[2]; gh[3] = hp[3];
    }
}

// ---------------------------------------------------------------------------
// Head: 256 blocks x 256 threads, 8 batch rows per block.
// ---------------------------------------------------------------------------
__global__ __launch_bounds__(256, 1) void head_kernel(
    const float* __restrict__ W1, const float* __restrict__ b1,
    const float* __restrict__ gamma, const float* __restrict__ beta,
    const float* __restrict__ mean, const float* __restrict__ var,
    const float* __restrict__ W2, const float* __restrict__ b2,
    float* __restrict__ out)
{
    extern __shared__ char smem[];
    float* fs  = (float*)smem;            // [8][64]
    float* W1s = fs + 8 * 64;             // [64][128]
    float* y1s = W1s + 64 * 128;          // [8][128]
    float* ls  = y1s + 8 * 128;           // [8][512]

    const int tid = threadIdx.x;
    const int g0  = blockIdx.x * 8;

    for (int i = tid; i < 8 * 64 / 4; i += 256)
        ((float4*)fs)[i] = ((const float4*)g_final)[g0 * 16 + i];
    for (int i = tid; i < 64 * 128 / 4; i += 256)
        ((float4*)W1s)[i] = ((const float4*)W1)[i];
    __syncthreads();

    // dense1 + relu + BN
    {
        const int c  = tid & 127;
        const int r0 = (tid >> 7) * 4;
        const float scale = gamma[c] * rsqrtf(var[c] + 1e-3f);
        const float shift = beta[c] - mean[c] * scale;
        const float bb = b1[c];
        #pragma unroll
        for (int r = r0; r < r0 + 4; r++) {
            float acc = bb;
            #pragma unroll 8
            for (int k = 0; k < 64; k++) acc += fs[r * 64 + k] * W1s[k * 128 + c];
            acc = fmaxf(acc, 0.0f);
            y1s[r * 128 + c] = acc * scale + shift;
        }
    }
    __syncthreads();

    // dense2: cols {2*tid, 2*tid+1}, k-packed f32x2
    {
        const int c0 = 2 * tid;
        unsigned long long acc[8][2];
        #pragma unroll
        for (int r = 0; r < 8; r++) { acc[r][0] = 0ULL; acc[r][1] = 0ULL; }

        #pragma unroll 4
        for (int kp2 = 0; kp2 < 32; kp2++) {
            const int k = 4 * kp2;
            float2 w0 = *(const float2*)(W2 + (size_t)(k    ) * OUTD + c0);
            float2 w1 = *(const float2*)(W2 + (size_t)(k + 1) * OUTD + c0);
            float2 w2 = *(const float2*)(W2 + (size_t)(k + 2) * OUTD + c0);
            float2 w3 = *(const float2*)(W2 + (size_t)(k + 3) * OUTD + c0);
            unsigned long long p01a = pack2(w0.x, w1.x);
            unsigned long long p23a = pack2(w2.x, w3.x);
            unsigned long long p01b = pack2(w0.y, w1.y);
            unsigned long long p23b = pack2(w2.y, w3.y);
            #pragma unroll
            for (int r = 0; r < 8; r++) {
                ulonglong2 y = *(const ulonglong2*)(y1s + r * 128 + k);
                FMA2(acc[r][0], y.x, p01a);
                FMA2(acc[r][0], y.y, p23a);
                FMA2(acc[r][1], y.x, p01b);
                FMA2(acc[r][1], y.y, p23b);
            }
        }
        const float bb0 = b2[c0], bb1 = b2[c0 + 1];
        #pragma unroll
        for (int r = 0; r < 8; r++) {
            float2 pa = unpack2(acc[r][0]);
            float2 pb = unpack2(acc[r][1]);
            ls[r * OUTD + c0]     = pa.x + pa.y + bb0;
            ls[r * OUTD + c0 + 1] = pb.x + pb.y + bb1;
        }
    }
    __syncthreads();

    // softmax: 8 warps, one row each
    {
        const int w = tid >> 5, lane = tid & 31;
        float v[16];
        float m = -1e30f;
        #pragma unroll
        for (int j = 0; j < 16; j++) {
            v[j] = ls[w * OUTD + lane + 32 * j];
            m = fmaxf(m, v[j]);
        }
        #pragma unroll
        for (int s = 16; s; s >>= 1) m = fmaxf(m, __shfl_xor_sync(0xffffffffu, m, s));
        float sum = 0.0f;
        #pragma unroll
        for (int j = 0; j < 16; j++) { v[j] = __expf(v[j] - m); sum += v[j]; }
        #pragma unroll
        for (int s = 16; s; s >>= 1) sum += __shfl_xor_sync(0xffffffffu, sum, s);
        const float inv = fast_rcp(sum);
        float* orow = out + (size_t)(g0 + w) * OUTD + lane;
        #pragma unroll
        for (int j = 0; j < 16; j++) orow[32 * j] = v[j] * inv;
    }
}

extern "C" void kernel_launch(void* const* d_in, const int* in_sizes, int n_in,
                              void* d_out, int out_size) {
    const float* X     = (const float*)d_in[0];
    const int*   seq   = (const int*)  d_in[1];
    const float* Wk    = (const float*)d_in[2];
    const float* bias  = (const float*)d_in[3];
    const float* W1    = (const float*)d_in[4];
    const float* b1    = (const float*)d_in[5];
    const float* gamma = (const float*)d_in[6];
    const float* beta  = (const float*)d_in[7];
    const float* mean  = (const float*)d_in[8];
    const float* var   = (const float*)d_in[9];
    const float* W2    = (const float*)d_in[10];
    const float* b2    = (const float*)d_in[11];
    float* out = (float*)d_out;

    cudaFuncSetAttribute(lstm_kernel, cudaFuncAttributeMaxDynamicSharedMemorySize, SMEM1);
    cudaFuncSetAttribute(head_kernel, cudaFuncAttributeMaxDynamicSharedMemorySize, SMEM_H);

    lstm_kernel<<<NBLK, 256, SMEM1>>>(X, seq, Wk, bias, 0, 150);
    lstm_kernel<<<NBLK, 256, SMEM1>>>(X, seq, Wk, bias, 150, 300);
    head_kernel<<<BATCH / 8, 256, SMEM_H>>>(W1, b1, gamma, beta, mean, var, W2, b2, out);
}

// round 17
// speedup vs baseline: 1.6212x; 1.1846x over previous
#include <cuda_runtime.h>

#define T_STEPS 300
#define DIMX 40
#define HID 64
#define KDIM 104          // DIMX + HID
#define NGATE 256
#define BATCH 2048
#define ROWS 14
#define NBLK 147
#define OUTD 512

// LSTM smem: A[14][104] + zs[14][256]  (B now lives in registers)
#define OFF_A   0
#define OFF_Z   5824
#define SMEM1   (5824 + 14336)

// head smem: fs[8*64] + W1s[64*128] + y1s[8*128] + ls[8*512]
#define SMEM_H  ((8*64 + 64*128 + 8*128 + 8*512) * 4)

__device__ float g_final[BATCH * HID];
__device__ float g_c[BATCH * HID];
__device__ float g_h[BATCH * HID];

__device__ __forceinline__ float fast_rcp(float x) {
    float y; asm("rcp.approx.f32 %0, %1;" : "=f"(y) : "f"(x)); return y;
}
__device__ __forceinline__ float tanh_fast(float x) {
    float y; asm("tanh.approx.f32 %0, %1;" : "=f"(y) : "f"(x)); return y;
}
__device__ __forceinline__ unsigned long long pack2(float a, float b) {
    unsigned long long r;
    asm("mov.b64 %0, {%1, %2};" : "=l"(r) : "f"(a), "f"(b));
    return r;
}
__device__ __forceinline__ float2 unpack2(unsigned long long v) {
    float2 r;
    asm("mov.b64 {%0, %1}, %2;" : "=f"(r.x), "=f"(r.y) : "l"(v));
    return r;
}
#define FMA2(d, a, b) asm("fma.rn.f32x2 %0, %1, %2, %0;" : "+l"(d) : "l"(a), "l"(b))

// ---------------------------------------------------------------------------
// Persistent LSTM — R2/R16 structure, but the step-invariant weight matrix
// moves from smem to REGISTERS via an intra-warp k-half split (R16 profile:
// L1=73% dominated by B reloads; FMA only 45%).
//
//   256 threads: tid = ct*2 + kw.  ct = col-pair (2 gate cols c0=2*ct),
//   kw = k-half (k in [kw*52, kw*52+52)).  Every thread covers ALL 14 rows.
//   Breg = 26 k-pairs x 2 cols = 104 regs;  acc = 14 rows x 2 = 56 regs
//   (~190 total — fits the 256-reg budget; R7's failure was 254+spills).
//
// GEMM per k-iter: 14 independent dual-broadcast LDS.128 of A (kw addrs
//   208B apart, disjoint banks -> 1 wf) + 56 FMA2. No B loads at all.
// Epilogue: hsum, ONE shfl_xor(1) per row (send the half you don't need,
//   receive the half you do), bias+activation (MUFU tanh), STS.32 to zs
//   (32 consecutive floats per warp-row -> 1 wf). Cell phase unchanged.
// ---------------------------------------------------------------------------
__global__ __launch_bounds__(256, 1) void lstm_kernel(
    const float* __restrict__ X,      // [B][T][40]
    const int*   __restrict__ seq,    // [B]
    const float* __restrict__ Wk,     // [104][256]
    const float* __restrict__ bias,   // [256]
    int t0, int t1)
{
    extern __shared__ char smem[];
    float* As = (float*)(smem + OFF_A);     // [14][104]
    float* zs = (float*)(smem + OFF_Z);     // [14][256]

    const int tid = threadIdx.x;
    const int g0  = blockIdx.x * ROWS;
    const int kw  = tid & 1;                // k half
    const int ct  = tid >> 1;               // col-pair 0..127
    const int c0  = 2 * ct;
    const int c   = c0 + kw;                // the gate column this thread activates
    const int gate = c >> 6;

    // ---- preload B slice into registers: 26 k-pairs x 2 cols ----
    unsigned long long Breg[26][2];
    {
        const int kbase = kw * 52;
        #pragma unroll
        for (int kp = 0; kp < 26; kp++) {
            const float* r0 = Wk + (size_t)(kbase + 2 * kp) * NGATE;
            const float* r1 = Wk + (size_t)(kbase + 2 * kp + 1) * NGATE;
            Breg[kp][0] = pack2(__ldg(r0 + c0),     __ldg(r1 + c0));
            Breg[kp][1] = pack2(__ldg(r0 + c0 + 1), __ldg(r1 + c0 + 1));
        }
    }

    // ---- init h region of A (zero or carried state) ----
    for (int i = tid; i < ROWS * HID; i += 256) {
        int r = i / HID, hh = i % HID;
        float hv = 0.0f;
        if (t0 > 0 && (g0 + r) < BATCH) hv = g_h[(size_t)(g0 + r) * HID + hh];
        As[r * KDIM + DIMX + hh] = hv;
    }

    // ---- x streaming: 560 elems/step, <=3 per thread ----
    const int e0 = tid;
    const int e1 = tid + 256;
    const int e2 = tid + 512;
    const bool v0 = (g0 + e0 / DIMX) < BATCH;
    const bool v1 = (e1 < ROWS * DIMX) && ((g0 + e1 / DIMX) < BATCH);
    const bool v2 = (e2 < ROWS * DIMX) && ((g0 + e2 / DIMX) < BATCH);
    const float* xp0 = X + (size_t)(g0 + e0 / DIMX) * (T_STEPS * DIMX) + (e0 % DIMX);
    const float* xp1 = X + (size_t)(g0 + (v1 ? e1 / DIMX : 0)) * (T_STEPS * DIMX) + (e1 % DIMX);
    const float* xp2 = X + (size_t)(g0 + (v2 ? e2 / DIMX : 0)) * (T_STEPS * DIMX) + (e2 % DIMX);

    // x_{t0}
    {
        const int off = t0 * DIMX;
        float a = v0 ? __ldg(xp0 + off) : 0.0f;
        float b = v1 ? __ldg(xp1 + off) : 0.0f;
        float cc = v2 ? __ldg(xp2 + off) : 0.0f;
        As[(e0 / DIMX) * KDIM + (e0 % DIMX)] = a;
        if (e1 < ROWS * DIMX) As[(e1 / DIMX) * KDIM + (e1 % DIMX)] = b;
        if (e2 < ROWS * DIMX) As[(e2 / DIMX) * KDIM + (e2 % DIMX)] = cc;
    }

    // ---- bias for this thread's single activated column (forget folded) ----
    const float biasr = __ldg(bias + c) + ((gate == 2) ? 1.0f : 0.0f);

    // ---- cell mapping: tid<224, 4 cells each (unchanged R2 structure) ----
    const int cr = tid >> 4;
    const int ch = (tid & 15) * 4;
    int myidx = -2;
    if (tid < 224 && (g0 + cr) < BATCH) myidx = seq[g0 + cr] - 1;
    float creg0 = 0.f, creg1 = 0.f, creg2 = 0.f, creg3 = 0.f;
    if (t0 > 0 && tid < 224 && (g0 + cr) < BATCH) {
        const float* cp = g_c + (size_t)(g0 + cr) * HID + ch;
        creg0 = cp[0]; creg1 = cp[1]; creg2 = cp[2]; creg3 = cp[3];
    }
    float* finalp = g_final + (size_t)(g0 + cr) * HID + ch;

    const float* Abase = As + kw * 52;

    __syncthreads();

    for (int t = t0; t < t1; t++) {
        // prefetch x_{t+1}
        float xr0 = 0.f, xr1 = 0.f, xr2 = 0.f;
        const bool pf = (t + 1 < T_STEPS);
        if (pf) {
            const int off = (t + 1) * DIMX;
            if (v0) xr0 = __ldg(xp0 + off);
            if (v1) xr1 = __ldg(xp1 + off);
            if (v2) xr2 = __ldg(xp2 + off);
        }

        // ---- GEMM: 14 rows x 2 cols over this thread's 52-k half ----
        unsigned long long acc[ROWS][2];
        #pragma unroll
        for (int r = 0; r < ROWS; r++) { acc[r][0] = 0ULL; acc[r][1] = 0ULL; }

        #pragma unroll
        for (int it = 0; it < 13; it++) {       // 4 k per iter (kp 2it, 2it+1)
            #pragma unroll
            for (int r = 0; r < ROWS; r++) {
                ulonglong2 a = *(const ulonglong2*)(Abase + r * KDIM + it * 4);
                FMA2(acc[r][0], a.x, Breg[2 * it][0]);
                FMA2(acc[r][1], a.x, Breg[2 * it][1]);
                FMA2(acc[r][0], a.y, Breg[2 * it + 1][0]);
                FMA2(acc[r][1], a.y, Breg[2 * it + 1][1]);
            }
        }

        // ---- epilogue: hsum + single-shfl k-merge + activation -> zs ----
        #pragma unroll
        for (int r = 0; r < ROWS; r++) {
            float2 p0 = unpack2(acc[r][0]);
            float2 p1 = unpack2(acc[r][1]);
            float v0s = p0.x + p0.y;            // col c0 partial (this k-half)
            float v1s = p1.x + p1.y;            // col c0+1 partial
            float mine  = kw ? v1s : v0s;       // the column I activate
            float yours = kw ? v0s : v1s;       // partner's column
            float z = mine + __shfl_xor_sync(0xffffffffu, yours, 1) + biasr;
            float a = (gate == 1) ? tanh_fast(z)
                                  : 0.5f * tanh_fast(0.5f * z) + 0.5f;
            zs[r * NGATE + c] = a;
        }
        __syncthreads();   // A reads done; zs visible

        // ---- stage x_{t+1} ----
        if (pf) {
            As[(e0 / DIMX) * KDIM + (e0 % DIMX)] = xr0;
            if (e1 < ROWS * DIMX) As[(e1 / DIMX) * KDIM + (e1 % DIMX)] = xr1;
            if (e2 < ROWS * DIMX) As[(e2 / DIMX) * KDIM + (e2 % DIMX)] = xr2;
        }

        // ---- cell update ----
        if (tid < 224) {
            const float* zrow = zs + cr * NGATE;
            float4 gi = *(const float4*)(zrow + ch);
            float4 gj = *(const float4*)(zrow + 64 + ch);
            float4 gf = *(const float4*)(zrow + 128 + ch);
            float4 go = *(const float4*)(zrow + 192 + ch);
            creg0 = creg0 * gf.x + gi.x * gj.x;
            creg1 = creg1 * gf.y + gi.y * gj.y;
            creg2 = creg2 * gf.z + gi.z * gj.z;
            creg3 = creg3 * gf.w + gi.w * gj.w;
            float h0 = tanh_fast(creg0) * go.x;
            float h1 = tanh_fast(creg1) * go.y;
            float h2 = tanh_fast(creg2) * go.z;
            float h3 = tanh_fast(creg3) * go.w;
            *(float4*)(As + cr * KDIM + DIMX + ch) = make_float4(h0, h1, h2, h3);
            if (t == myidx) {
                finalp[0] = h0; finalp[1] = h1; finalp[2] = h2; finalp[3] = h3;
            }
        }
        __syncthreads();   // A ready for next step
    }

    // ---- save carry state if more steps remain ----
    if (t1 < T_STEPS && tid < 224 && (g0 + cr) < BATCH) {
        float* cp = g_c + (size_t)(g0 + cr) * HID + ch;
        cp[0] = creg0; cp[1] = creg1; cp[2] = creg2; cp[3] = creg3;
        const float* hp = As + cr * KDIM + DIMX + ch;
        float* gh = g_h + (size_t)(g0 + cr) * HID + ch;
        gh[0] = hp[0]; gh[1] = hp[1]; gh[2] = hp[2]; gh[3] = hp[3];
    }
}

// ---------------------------------------------------------------------------
// Head: 256 blocks x 256 threads, 8 batch rows per block.
// ---------------------------------------------------------------------------
__global__ __launch_bounds__(256, 1) void head_kernel(
    const float* __restrict__ W1, const float* __restrict__ b1,
    const float* __restrict__ gamma, const float* __restrict__ beta,
    const float* __restrict__ mean, const float* __restrict__ var,
    const float* __restrict__ W2, const float* __restrict__ b2,
    float* __restrict__ out)
{
    extern __shared__ char smem[];
    float* fs  = (float*)smem;            // [8][64]
    float* W1s = fs + 8 * 64;             // [64][128]
    float* y1s = W1s + 64 * 128;          // [8][128]
    float* ls  = y1s + 8 * 128;           // [8][512]

    const int tid = threadIdx.x;
    const int g0  = blockIdx.x * 8;

    for (int i = tid; i < 8 * 64 / 4; i += 256)
        ((float4*)fs)[i] = ((const float4*)g_final)[g0 * 16 + i];
    for (int i = tid; i < 64 * 128 / 4; i += 256)
        ((float4*)W1s)[i] = ((const float4*)W1)[i];
    __syncthreads();

    // dense1 + relu + BN
    {
        const int cc = tid & 127;
        const int r0 = (tid >> 7) * 4;
        const float scale = gamma[cc] * rsqrtf(var[cc] + 1e-3f);
        const float shift = beta[cc] - mean[cc] * scale;
        const float bb = b1[cc];
        #pragma unroll
        for (int r = r0; r < r0 + 4; r++) {
            float acc = bb;
            #pragma unroll 8
            for (int k = 0; k < 64; k++) acc += fs[r * 64 + k] * W1s[k * 128 + cc];
            acc = fmaxf(acc, 0.0f);
            y1s[r * 128 + cc] = acc * scale + shift;
        }
    }
    __syncthreads();

    // dense2: cols {2*tid, 2*tid+1}, k-packed f32x2
    {
        const int c0 = 2 * tid;
        unsigned long long acc[8][2];
        #pragma unroll
        for (int r = 0; r < 8; r++) { acc[r][0] = 0ULL; acc[r][1] = 0ULL; }

        #pragma unroll 4
        for (int kp2 = 0; kp2 < 32; kp2++) {
            const int k = 4 * kp2;
            float2 w0 = *(const float2*)(W2 + (size_t)(k    ) * OUTD + c0);
            float2 w1 = *(const float2*)(W2 + (size_t)(k + 1) * OUTD + c0);
            float2 w2 = *(const float2*)(W2 + (size_t)(k + 2) * OUTD + c0);
            float2 w3 = *(const float2*)(W2 + (size_t)(k + 3) * OUTD + c0);
            unsigned long long p01a = pack2(w0.x, w1.x);
            unsigned long long p23a = pack2(w2.x, w3.x);
            unsigned long long p01b = pack2(w0.y, w1.y);
            unsigned long long p23b = pack2(w2.y, w3.y);
            #pragma unroll
            for (int r = 0; r < 8; r++) {
                ulonglong2 y = *(const ulonglong2*)(y1s + r * 128 + k);
                FMA2(acc[r][0], y.x, p01a);
                FMA2(acc[r][0], y.y, p23a);
                FMA2(acc[r][1], y.x, p01b);
                FMA2(acc[r][1], y.y, p23b);
            }
        }
        const float bb0 = b2[c0], bb1 = b2[c0 + 1];
        #pragma unroll
        for (int r = 0; r < 8; r++) {
            float2 pa = unpack2(acc[r][0]);
            float2 pb = unpack2(acc[r][1]);
            ls[r * OUTD + c0]     = pa.x + pa.y + bb0;
            ls[r * OUTD + c0 + 1] = pb.x + pb.y + bb1;
        }
    }
    __syncthreads();

    // softmax: 8 warps, one row each
    {
        const int w = tid >> 5, lane = tid & 31;
        float v[16];
        float m = -1e30f;
        #pragma unroll
        for (int j = 0; j < 16; j++) {
            v[j] = ls[w * OUTD + lane + 32 * j];
            m = fmaxf(m, v[j]);
        }
        #pragma unroll
        for (int s = 16; s; s >>= 1) m = fmaxf(m, __shfl_xor_sync(0xffffffffu, m, s));
        float sum = 0.0f;
        #pragma unroll
        for (int j = 0; j < 16; j++) { v[j] = __expf(v[j] - m); sum += v[j]; }
        #pragma unroll
        for (int s = 16; s; s >>= 1) sum += __shfl_xor_sync(0xffffffffu, sum, s);
        const float inv = fast_rcp(sum);
        float* orow = out + (size_t)(g0 + w) * OUTD + lane;
        #pragma unroll
        for (int j = 0; j < 16; j++) orow[32 * j] = v[j] * inv;
    }
}

extern "C" void kernel_launch(void* const* d_in, const int* in_sizes, int n_in,
                              void* d_out, int out_size) {
    const float* X     = (const float*)d_in[0];
    const int*   seq   = (const int*)  d_in[1];
    const float* Wk    = (const float*)d_in[2];
    const float* bias  = (const float*)d_in[3];
    const float* W1    = (const float*)d_in[4];
    const float* b1    = (const float*)d_in[5];
    const float* gamma = (const float*)d_in[6];
    const float* beta  = (const float*)d_in[7];
    const float* mean  = (const float*)d_in[8];
    const float* var   = (const float*)d_in[9];
    const float* W2    = (const float*)d_in[10];
    const float* b2    = (const float*)d_in[11];
    float* out = (float*)d_out;

    cudaFuncSetAttribute(lstm_kernel, cudaFuncAttributeMaxDynamicSharedMemorySize, SMEM1);
    cudaFuncSetAttribute(head_kernel, cudaFuncAttributeMaxDynamicSharedMemorySize, SMEM_H);

    lstm_kernel<<<NBLK, 256, SMEM1>>>(X, seq, Wk, bias, 0, 150);
    lstm_kernel<<<NBLK, 256, SMEM1>>>(X, seq, Wk, bias, 150, 300);
    head_kernel<<<BATCH / 8, 256, SMEM_H>>>(W1, b1, gamma, beta, mean, var, W2, b2, out);
}